// round 1
// baseline (speedup 1.0000x reference)
#include <cuda_runtime.h>
#include <math.h>

#define BN 4
#define CC 256
#define CQN 32
#define NN 4096
#define TI 64
#define TJ 64

// ---------------- scratch (device globals; no allocation allowed) ----------
__device__ float g_q[(size_t)BN * NN * CQN];           // [b][n][32], masked
__device__ float g_k[(size_t)BN * NN * CQN];           // [b][n][32], masked
__device__ float g_v[(size_t)BN * NN * CC];            // [b][n][256]

// ---------------- projection kernel ----------------------------------------
// One block = (b, 64-pixel tile). x tile [256][64] staged in smem.
// Each thread: fixed pixel j = tid&63, output-group og = tid>>6.
// 4-output register blocking: 4 LDS + 4 LDG.128 + 16 FMA per c4 step.

__device__ __forceinline__ void proj_quad(const float4* __restrict__ W4, int o0,
                                          const float* __restrict__ bias,
                                          const float* __restrict__ xs, int j,
                                          float acc[4])
{
    acc[0] = bias[o0 + 0];
    acc[1] = bias[o0 + 1];
    acc[2] = bias[o0 + 2];
    acc[3] = bias[o0 + 3];
#pragma unroll 8
    for (int c4 = 0; c4 < CC / 4; c4++) {
        float x0 = xs[(c4 * 4 + 0) * 64 + j];
        float x1 = xs[(c4 * 4 + 1) * 64 + j];
        float x2 = xs[(c4 * 4 + 2) * 64 + j];
        float x3 = xs[(c4 * 4 + 3) * 64 + j];
#pragma unroll
        for (int r = 0; r < 4; r++) {
            float4 w = W4[(o0 + r) * (CC / 4) + c4];
            acc[r] = fmaf(w.x, x0, acc[r]);
            acc[r] = fmaf(w.y, x1, acc[r]);
            acc[r] = fmaf(w.z, x2, acc[r]);
            acc[r] = fmaf(w.w, x3, acc[r]);
        }
    }
}

__global__ __launch_bounds__(256) void proj_kernel(
    const float* __restrict__ x, const float* __restrict__ mask,
    const float* __restrict__ Wq, const float* __restrict__ bq,
    const float* __restrict__ Wk, const float* __restrict__ bk,
    const float* __restrict__ Wv, const float* __restrict__ bv)
{
    extern __shared__ float xs[];  // [256][64] = 64 KB
    const int b   = blockIdx.y;
    const int n0  = blockIdx.x * 64;
    const int tid = threadIdx.x;

    const float* xb = x + (size_t)b * CC * NN;
    for (int idx = tid; idx < CC * 64; idx += 256) {
        int c = idx >> 6, j = idx & 63;
        xs[c * 64 + j] = xb[(size_t)c * NN + n0 + j];
    }
    __syncthreads();

    const int j  = tid & 63;
    const int og = tid >> 6;        // 0..3
    const int n  = n0 + j;
    const float m = mask[b * NN + n];

    float acc[4];

    // q and k: 32 outputs each -> 2 quads per thread
#pragma unroll
    for (int p = 0; p < 2; p++) {
        int o0 = og * 4 + p * 16;
        proj_quad((const float4*)Wq, o0, bq, xs, j, acc);
        float4 rq = make_float4(acc[0] * m, acc[1] * m, acc[2] * m, acc[3] * m);
        *(float4*)&g_q[((size_t)b * NN + n) * CQN + o0] = rq;

        proj_quad((const float4*)Wk, o0, bk, xs, j, acc);
        float4 rk = make_float4(acc[0] * m, acc[1] * m, acc[2] * m, acc[3] * m);
        *(float4*)&g_k[((size_t)b * NN + n) * CQN + o0] = rk;
    }

    // v: 256 outputs -> 16 quads per thread (no mask)
#pragma unroll 4
    for (int p = 0; p < 16; p++) {
        int o0 = og * 4 + p * 16;
        proj_quad((const float4*)Wv, o0, bv, xs, j, acc);
        *(float4*)&g_v[((size_t)b * NN + n) * CC + o0] =
            make_float4(acc[0], acc[1], acc[2], acc[3]);
    }
}

// ---------------- flash attention kernel ------------------------------------
// One block = (b, 64-row i tile). Online softmax over 64 j-tiles.
// Thread layout: tr = tid>>4 (row group, 4 rows each), tc = tid&15.
// S phase: 4x4 micro-tile per thread. PV: O[4][16] regs, c = tc*4 + 64k + kk.

#define SQ_STRIDE 33
#define SP_STRIDE 65

__global__ __launch_bounds__(256, 2) void attn_kernel(
    const float* __restrict__ x, const float* __restrict__ gamma_p,
    float* __restrict__ out)
{
    extern __shared__ float sm[];
    float* sQ = sm;                       // 64 x 33
    float* sK = sQ + 64 * SQ_STRIDE;      // 64 x 33
    float* sP = sK + 64 * SQ_STRIDE;      // 64 x 65
    float* sV = sP + 64 * SP_STRIDE;      // 64 x 256

    const int b   = blockIdx.y;
    const int i0  = blockIdx.x * TI;
    const int tid = threadIdx.x;
    const int tr  = tid >> 4;   // 0..15
    const int tc  = tid & 15;   // 0..15

    // load Q tile (persists across j loop)
    const float* qb = g_q + ((size_t)b * NN + i0) * CQN;
    for (int idx = tid; idx < TI * CQN; idx += 256) {
        int i = idx >> 5, c = idx & 31;
        sQ[i * SQ_STRIDE + c] = qb[i * CQN + c];
    }

    float O[4][16];
#pragma unroll
    for (int ii = 0; ii < 4; ii++)
#pragma unroll
        for (int cc = 0; cc < 16; cc++) O[ii][cc] = 0.f;

    float mrow[4] = {-INFINITY, -INFINITY, -INFINITY, -INFINITY};
    float lrow[4] = {0.f, 0.f, 0.f, 0.f};

    for (int jt = 0; jt < NN / TJ; jt++) {
        __syncthreads();   // prev-iter PV done (and Q load on first iter)

        // load K, V tiles
        const float* kb = g_k + ((size_t)b * NN + jt * TJ) * CQN;
        for (int idx = tid; idx < TJ * CQN; idx += 256) {
            int jj = idx >> 5, c = idx & 31;
            sK[jj * SQ_STRIDE + c] = kb[jj * CQN + c];
        }
        const float4* vb4 = (const float4*)(g_v + ((size_t)b * NN + jt * TJ) * CC);
        float4* sV4 = (float4*)sV;
        for (int idx = tid; idx < TJ * CC / 4; idx += 256)
            sV4[idx] = vb4[idx];
        __syncthreads();

        // ---- S = Q K^T (4x4 micro tile) ----
        float s[4][4];
#pragma unroll
        for (int ii = 0; ii < 4; ii++)
#pragma unroll
            for (int jj = 0; jj < 4; jj++) s[ii][jj] = 0.f;

#pragma unroll 4
        for (int c = 0; c < CQN; c++) {
            float q0 = sQ[(tr * 4 + 0) * SQ_STRIDE + c];
            float q1 = sQ[(tr * 4 + 1) * SQ_STRIDE + c];
            float q2 = sQ[(tr * 4 + 2) * SQ_STRIDE + c];
            float q3 = sQ[(tr * 4 + 3) * SQ_STRIDE + c];
            float k0 = sK[(tc * 4 + 0) * SQ_STRIDE + c];
            float k1 = sK[(tc * 4 + 1) * SQ_STRIDE + c];
            float k2 = sK[(tc * 4 + 2) * SQ_STRIDE + c];
            float k3 = sK[(tc * 4 + 3) * SQ_STRIDE + c];
            float qq[4] = {q0, q1, q2, q3};
            float kk_[4] = {k0, k1, k2, k3};
#pragma unroll
            for (int ii = 0; ii < 4; ii++)
#pragma unroll
                for (int jj = 0; jj < 4; jj++)
                    s[ii][jj] = fmaf(qq[ii], kk_[jj], s[ii][jj]);
        }

        // ---- online softmax ----
        float scl[4];
#pragma unroll
        for (int ii = 0; ii < 4; ii++) {
            float v = fmaxf(fmaxf(s[ii][0], s[ii][1]), fmaxf(s[ii][2], s[ii][3]));
#pragma unroll
            for (int off = 8; off; off >>= 1)
                v = fmaxf(v, __shfl_xor_sync(0xffffffffu, v, off));
            float mnew = fmaxf(mrow[ii], v);
            scl[ii] = __expf(mrow[ii] - mnew);
            float rs = 0.f;
#pragma unroll
            for (int jj = 0; jj < 4; jj++) {
                float p = __expf(s[ii][jj] - mnew);
                sP[(tr * 4 + ii) * SP_STRIDE + tc * 4 + jj] = p;
                rs += p;
            }
#pragma unroll
            for (int off = 8; off; off >>= 1)
                rs += __shfl_xor_sync(0xffffffffu, rs, off);
            mrow[ii] = mnew;
            lrow[ii] = lrow[ii] * scl[ii] + rs;
        }
#pragma unroll
        for (int ii = 0; ii < 4; ii++) {
            float sc = scl[ii];
#pragma unroll
            for (int cc = 0; cc < 16; cc++) O[ii][cc] *= sc;
        }
        __syncthreads();   // sP visible to all

        // ---- O += P V ----
#pragma unroll 2
        for (int jj = 0; jj < TJ; jj++) {
            float pp[4];
#pragma unroll
            for (int ii = 0; ii < 4; ii++)
                pp[ii] = sP[(tr * 4 + ii) * SP_STRIDE + jj];
#pragma unroll
            for (int k = 0; k < 4; k++) {
                float4 v = *(const float4*)&sV[jj * CC + tc * 4 + 64 * k];
                float vv[4] = {v.x, v.y, v.z, v.w};
#pragma unroll
                for (int ii = 0; ii < 4; ii++)
#pragma unroll
                    for (int kk = 0; kk < 4; kk++)
                        O[ii][k * 4 + kk] = fmaf(pp[ii], vv[kk], O[ii][k * 4 + kk]);
            }
        }
    }

    // ---- epilogue: out = gamma * O/l + x ----
    const float g = *gamma_p;
    float inv[4];
#pragma unroll
    for (int ii = 0; ii < 4; ii++) inv[ii] = 1.f / lrow[ii];

#pragma unroll
    for (int k = 0; k < 4; k++) {
#pragma unroll
        for (int kk = 0; kk < 4; kk++) {
            int c = tc * 4 + 64 * k + kk;
            size_t base = ((size_t)(b * CC + c)) * NN + i0 + tr * 4;
            float4 xr = *(const float4*)&x[base];
            float4 o4;
            o4.x = fmaf(g, O[0][k * 4 + kk] * inv[0], xr.x);
            o4.y = fmaf(g, O[1][k * 4 + kk] * inv[1], xr.y);
            o4.z = fmaf(g, O[2][k * 4 + kk] * inv[2], xr.z);
            o4.w = fmaf(g, O[3][k * 4 + kk] * inv[3], xr.w);
            *(float4*)&out[base] = o4;
        }
    }
}

// ---------------- launch ----------------------------------------------------
extern "C" void kernel_launch(void* const* d_in, const int* in_sizes, int n_in,
                              void* d_out, int out_size)
{
    const float* x     = (const float*)d_in[0];
    const float* mask  = (const float*)d_in[1];
    const float* Wq    = (const float*)d_in[2];
    const float* bq    = (const float*)d_in[3];
    const float* Wk    = (const float*)d_in[4];
    const float* bk    = (const float*)d_in[5];
    const float* Wv    = (const float*)d_in[6];
    const float* bv    = (const float*)d_in[7];
    const float* gamma = (const float*)d_in[8];
    float* out = (float*)d_out;

    const int proj_smem = CC * 64 * (int)sizeof(float);                 // 65536
    const int attn_smem = (64 * SQ_STRIDE * 2 + 64 * SP_STRIDE + 64 * CC)
                          * (int)sizeof(float);                          // 99072

    cudaFuncSetAttribute(proj_kernel, cudaFuncAttributeMaxDynamicSharedMemorySize, proj_smem);
    cudaFuncSetAttribute(attn_kernel, cudaFuncAttributeMaxDynamicSharedMemorySize, attn_smem);

    dim3 grid(NN / 64, BN);
    proj_kernel<<<grid, 256, proj_smem>>>(x, mask, Wq, bq, Wk, bk, Wv, bv);
    attn_kernel<<<grid, 256, attn_smem>>>(x, gamma, out);
}

// round 7
// speedup vs baseline: 2.7934x; 2.7934x over previous
#include <cuda_runtime.h>
#include <cuda_bf16.h>
#include <stdint.h>
#include <math.h>

#define BN  4
#define CCH 256
#define CQ  32
#define NN  4096
#define NT  64

// ---------------- bf16 split operand globals --------------------------------
__device__ __align__(128) __nv_bfloat16 g_qhi[(size_t)BN * NN * CQ];
__device__ __align__(128) __nv_bfloat16 g_qlo[(size_t)BN * NN * CQ];
__device__ __align__(128) __nv_bfloat16 g_khi[(size_t)BN * NN * CQ];
__device__ __align__(128) __nv_bfloat16 g_klo[(size_t)BN * NN * CQ];
__device__ __align__(128) __nv_bfloat16 g_vhi[(size_t)BN * CCH * NN];   // [b][c][n]

// ---------------- helpers ----------------------------------------------------
__device__ __forceinline__ uint32_t smem_u32(const void* p) {
    uint32_t a;
    asm("{ .reg .u64 t; cvta.to.shared.u64 t, %1; cvt.u32.u64 %0, t; }" : "=r"(a) : "l"(p));
    return a;
}
__device__ __forceinline__ uint32_t swz(uint32_t x) { return x ^ ((x >> 3) & 0x70); }

__device__ __forceinline__ void cp16(uint32_t dst, const void* src) {
    asm volatile("cp.async.cg.shared.global [%0], [%1], 16;" :: "r"(dst), "l"(src) : "memory");
}
__device__ __forceinline__ void cp_commit() { asm volatile("cp.async.commit_group;" ::: "memory"); }
__device__ __forceinline__ void cp_wait0()  { asm volatile("cp.async.wait_group 0;" ::: "memory"); }

__device__ __forceinline__ void ldm_x4(uint32_t* r, uint32_t addr) {
    asm volatile("ldmatrix.sync.aligned.m8n8.x4.shared.b16 {%0,%1,%2,%3}, [%4];"
                 : "=r"(r[0]), "=r"(r[1]), "=r"(r[2]), "=r"(r[3]) : "r"(addr));
}
__device__ __forceinline__ void mma16816(float* c, const uint32_t* a, uint32_t b0, uint32_t b1) {
    asm volatile("mma.sync.aligned.m16n8k16.row.col.f32.bf16.bf16.f32 "
                 "{%0,%1,%2,%3}, {%4,%5,%6,%7}, {%8,%9}, {%0,%1,%2,%3};"
                 : "+f"(c[0]), "+f"(c[1]), "+f"(c[2]), "+f"(c[3])
                 : "r"(a[0]), "r"(a[1]), "r"(a[2]), "r"(a[3]), "r"(b0), "r"(b1));
}
__device__ __forceinline__ uint32_t packbf2(float a, float b) {
    __nv_bfloat162 t = __floats2bfloat162_rn(a, b);
    return *(uint32_t*)&t;
}

// ---------------- projection kernel (FFMA) ----------------------------------
__device__ __forceinline__ void proj_quad(const float4* __restrict__ W4, int o0,
                                          const float* __restrict__ bias,
                                          const float* __restrict__ xs, int j,
                                          float acc[4])
{
    acc[0] = bias[o0 + 0]; acc[1] = bias[o0 + 1];
    acc[2] = bias[o0 + 2]; acc[3] = bias[o0 + 3];
#pragma unroll 8
    for (int c4 = 0; c4 < CCH / 4; c4++) {
        float x0 = xs[(c4 * 4 + 0) * 32 + j];
        float x1 = xs[(c4 * 4 + 1) * 32 + j];
        float x2 = xs[(c4 * 4 + 2) * 32 + j];
        float x3 = xs[(c4 * 4 + 3) * 32 + j];
#pragma unroll
        for (int r = 0; r < 4; r++) {
            float4 w = W4[(o0 + r) * (CCH / 4) + c4];
            acc[r] = fmaf(w.x, x0, acc[r]);
            acc[r] = fmaf(w.y, x1, acc[r]);
            acc[r] = fmaf(w.z, x2, acc[r]);
            acc[r] = fmaf(w.w, x3, acc[r]);
        }
    }
}

__device__ __forceinline__ void store_qk_split(__nv_bfloat16* hi_arr, __nv_bfloat16* lo_arr,
                                               size_t base, const float v[4])
{
    __nv_bfloat162 h01 = __floats2bfloat162_rn(v[0], v[1]);
    __nv_bfloat162 h23 = __floats2bfloat162_rn(v[2], v[3]);
    float l0 = v[0] - __bfloat162float(h01.x);
    float l1 = v[1] - __bfloat162float(h01.y);
    float l2 = v[2] - __bfloat162float(h23.x);
    float l3 = v[3] - __bfloat162float(h23.y);
    __nv_bfloat162 L01 = __floats2bfloat162_rn(l0, l1);
    __nv_bfloat162 L23 = __floats2bfloat162_rn(l2, l3);
    uint2 hw = make_uint2(*(uint32_t*)&h01, *(uint32_t*)&h23);
    uint2 lw = make_uint2(*(uint32_t*)&L01, *(uint32_t*)&L23);
    *(uint2*)&hi_arr[base] = hw;
    *(uint2*)&lo_arr[base] = lw;
}

__global__ __launch_bounds__(256, 2) void proj_kernel(
    const float* __restrict__ x, const float* __restrict__ mask,
    const float* __restrict__ Wq, const float* __restrict__ bq,
    const float* __restrict__ Wk, const float* __restrict__ bk,
    const float* __restrict__ Wv, const float* __restrict__ bv)
{
    extern __shared__ float xs[];   // [256][32] floats = 32 KB
    const int b   = blockIdx.y;
    const int n0  = blockIdx.x * 32;
    const int tid = threadIdx.x;

    const float* xb = x + (size_t)b * CCH * NN;
    for (int idx = tid; idx < 2048; idx += 256) {
        int c = idx >> 3, f = idx & 7;
        ((float4*)xs)[c * 8 + f] = *(const float4*)(xb + (size_t)c * NN + n0 + f * 4);
    }
    __syncthreads();

    const int j  = tid & 31;
    const int og = tid >> 5;          // 0..7
    const int n  = n0 + j;
    const float m = mask[b * NN + n];

    float acc[4], vm[4];

    proj_quad((const float4*)Wq, og * 4, bq, xs, j, acc);
#pragma unroll
    for (int r = 0; r < 4; r++) vm[r] = acc[r] * m;
    store_qk_split(g_qhi, g_qlo, ((size_t)(b * NN + n)) * CQ + og * 4, vm);

    proj_quad((const float4*)Wk, og * 4, bk, xs, j, acc);
#pragma unroll
    for (int r = 0; r < 4; r++) vm[r] = acc[r] * m;
    store_qk_split(g_khi, g_klo, ((size_t)(b * NN + n)) * CQ + og * 4, vm);

#pragma unroll 2
    for (int p = 0; p < 8; p++) {
        int o0 = og * 4 + p * 32;
        proj_quad((const float4*)Wv, o0, bv, xs, j, acc);
#pragma unroll
        for (int r = 0; r < 4; r++)
            g_vhi[((size_t)(b * CCH + o0 + r)) * NN + n] = __float2bfloat16(acc[r]);
    }
}

// ---------------- mma.sync flash attention -----------------------------------
// CTA: 512 thr (16 warps), b fixed, 128 query rows. warp (mw,ch): rows mw*16,
// cols ch*128. smem rows are 128B with XOR swizzle.
//   sQ: 128 rows  [32 hi bf16 | 32 lo bf16]      (16 KB, loaded once)
//   sK: 2 x 64 rows  [32 hi | 32 lo]             (16 KB)
//   sV: 2 x 256 rows [64 j bf16]                 (64 KB)

#define OFF_Q 0
#define OFF_K 16384
#define OFF_V 32768
#define SMEM_ATTN 98304

__device__ __forceinline__ void load_kv_tile(uint32_t sb, int b, int j0, int buf, int tid)
{
    {   // K hi/lo: 512 chunks, one per thread
        int row = tid >> 3, c8 = tid & 7;
        const __nv_bfloat16* src = (c8 < 4 ? g_khi : g_klo)
            + ((size_t)(b * NN) + j0 + row) * CQ + (c8 & 3) * 8;
        cp16(sb + OFF_K + buf * 8192 + swz(row * 128 + (c8 < 4 ? 0 : 64) + (c8 & 3) * 16), src);
    }
#pragma unroll
    for (int q = 0; q < 4; q++) {   // V: 2048 chunks
        int idx = tid + q * 512;
        int c = idx >> 3, c8 = idx & 7;
        const __nv_bfloat16* src = g_vhi + ((size_t)(b * CCH) + c) * NN + j0 + c8 * 8;
        cp16(sb + OFF_V + buf * 32768 + swz(c * 128 + c8 * 16), src);
    }
}

__global__ __launch_bounds__(512, 1) void attn_kernel(
    const float* __restrict__ x, const float* __restrict__ gamma_p,
    float* __restrict__ out)
{
    extern __shared__ char smc[];
    const uint32_t sb = smem_u32(smc);
    const int b    = blockIdx.y;
    const int i0   = blockIdx.x * 128;
    const int tid  = threadIdx.x;
    const int lane = tid & 31;
    const int wid  = tid >> 5;
    const int mw   = wid & 7;    // row block (16 rows)
    const int ch   = wid >> 3;   // col half (128 cols)

    // ---- prologue: Q + K/V tile 0 ------------------------------------------
#pragma unroll
    for (int q = 0; q < 2; q++) {   // Q: 1024 chunks
        int idx = tid + q * 512;
        int row = idx >> 3, c8 = idx & 7;
        const __nv_bfloat16* src = (c8 < 4 ? g_qhi : g_qlo)
            + ((size_t)(b * NN) + i0 + row) * CQ + (c8 & 3) * 8;
        cp16(sb + OFF_Q + swz(row * 128 + (c8 < 4 ? 0 : 64) + (c8 & 3) * 16), src);
    }
    load_kv_tile(sb, b, 0, 0, tid);
    cp_commit();
    cp_wait0();
    __syncthreads();

    // ---- Q A-fragments (held in regs for whole kernel) ----------------------
    const int arow  = mw * 16 + (lane & 7) + 8 * ((lane >> 3) & 1);
    const int acol8 = 8 * (lane >> 4);             // elem offset within k-step
    uint32_t qh[2][4], ql[2][4];
#pragma unroll
    for (int kst = 0; kst < 2; kst++) {
        ldm_x4(qh[kst], sb + OFF_Q + swz(arow * 128 + (kst * 16 + acol8) * 2));
        ldm_x4(ql[kst], sb + OFF_Q + swz(arow * 128 + 64 + (kst * 16 + acol8) * 2));
    }

    // B-fragment lane geometry (shared by K and V ldmatrix)
    const int brow  = (lane & 7) + 8 * (lane >> 4);
    const int bcol8 = 8 * ((lane >> 3) & 1);

    float O[16][4];
#pragma unroll
    for (int n = 0; n < 16; n++)
#pragma unroll
        for (int r = 0; r < 4; r++) O[n][r] = 0.f;
    float ls0 = 0.f, ls1 = 0.f;

    for (int jt = 0; jt < NT; jt++) {
        const int buf = jt & 1;
        if (jt + 1 < NT) { load_kv_tile(sb, b, (jt + 1) * 64, (jt + 1) & 1, tid); cp_commit(); }

        const uint32_t kb = sb + OFF_K + buf * 8192;
        const uint32_t vb = sb + OFF_V + buf * 32768;

#pragma unroll
        for (int h = 0; h < 2; h++) {           // 32 j-cols per half
            float C[4][4];
#pragma unroll
            for (int n = 0; n < 4; n++)
#pragma unroll
                for (int r = 0; r < 4; r++) C[n][r] = 0.f;

#pragma unroll
            for (int p2 = 0; p2 < 2; p2++) {
                const int jb = h * 32 + p2 * 16;
#pragma unroll
                for (int kst = 0; kst < 2; kst++) {
                    uint32_t khf[4], klf[4];
                    ldm_x4(khf, kb + swz((jb + brow) * 128 + (kst * 16 + bcol8) * 2));
                    ldm_x4(klf, kb + swz((jb + brow) * 128 + 64 + (kst * 16 + bcol8) * 2));
                    mma16816(C[p2 * 2 + 0], qh[kst], khf[0], khf[1]);
                    mma16816(C[p2 * 2 + 1], qh[kst], khf[2], khf[3]);
                    mma16816(C[p2 * 2 + 0], qh[kst], klf[0], klf[1]);
                    mma16816(C[p2 * 2 + 1], qh[kst], klf[2], klf[3]);
                    mma16816(C[p2 * 2 + 0], ql[kst], khf[0], khf[1]);
                    mma16816(C[p2 * 2 + 1], ql[kst], khf[2], khf[3]);
                }
            }

            // exp + split to P hi/lo A-fragments (2 local k-steps)
            uint32_t ph[2][4], pl[2][4];
#pragma unroll
            for (int t = 0; t < 2; t++) {
                float e[8];
#pragma unroll
                for (int r = 0; r < 4; r++) e[r]     = __expf(C[2 * t][r]);
#pragma unroll
                for (int r = 0; r < 4; r++) e[4 + r] = __expf(C[2 * t + 1][r]);
                ls0 += e[0] + e[1] + e[4] + e[5];
                ls1 += e[2] + e[3] + e[6] + e[7];
                float eh[8], el[8];
#pragma unroll
                for (int r = 0; r < 8; r++) {
                    eh[r] = __bfloat162float(__float2bfloat16(e[r]));
                    el[r] = e[r] - eh[r];
                }
                ph[t][0] = packbf2(eh[0], eh[1]); ph[t][1] = packbf2(eh[2], eh[3]);
                ph[t][2] = packbf2(eh[4], eh[5]); ph[t][3] = packbf2(eh[6], eh[7]);
                pl[t][0] = packbf2(el[0], el[1]); pl[t][1] = packbf2(el[2], el[3]);
                pl[t][2] = packbf2(el[4], el[5]); pl[t][3] = packbf2(el[6], el[7]);
            }

            // PV for this half's 2 k-steps
#pragma unroll
            for (int t = 0; t < 2; t++) {
                const int k0 = h * 32 + t * 16;
#pragma unroll
                for (int cbp = 0; cbp < 8; cbp++) {
                    const int cb = ch * 128 + cbp * 16;
                    uint32_t vf[4];
                    ldm_x4(vf, vb + swz((cb + brow) * 128 + (k0 + bcol8) * 2));
                    mma16816(O[cbp * 2 + 0], ph[t], vf[0], vf[1]);
                    mma16816(O[cbp * 2 + 1], ph[t], vf[2], vf[3]);
                    mma16816(O[cbp * 2 + 0], pl[t], vf[0], vf[1]);
                    mma16816(O[cbp * 2 + 1], pl[t], vf[2], vf[3]);
                }
            }
        }

        __syncthreads();                 // all warps done reading buf
        if (jt + 1 < NT) { cp_wait0(); __syncthreads(); }
    }

    // ---- epilogue ------------------------------------------------------------
    ls0 += __shfl_xor_sync(0xffffffffu, ls0, 1);
    ls0 += __shfl_xor_sync(0xffffffffu, ls0, 2);
    ls1 += __shfl_xor_sync(0xffffffffu, ls1, 1);
    ls1 += __shfl_xor_sync(0xffffffffu, ls1, 2);
    const float linv0 = 1.f / ls0;
    const float linv1 = 1.f / ls1;
    const float g = *gamma_p;
    const int r0 = i0 + mw * 16 + (lane >> 2);

#pragma unroll
    for (int nb = 0; nb < 16; nb++) {
        const int cc = ch * 128 + nb * 8 + (lane & 3) * 2;
        const size_t b0 = ((size_t)(b * CCH + cc)) * NN + r0;
        const size_t b1 = b0 + NN;
        out[b0]     = fmaf(g, O[nb][0] * linv0, x[b0]);
        out[b1]     = fmaf(g, O[nb][1] * linv0, x[b1]);
        out[b0 + 8] = fmaf(g, O[nb][2] * linv1, x[b0 + 8]);
        out[b1 + 8] = fmaf(g, O[nb][3] * linv1, x[b1 + 8]);
    }
}

// ---------------- launch -----------------------------------------------------
extern "C" void kernel_launch(void* const* d_in, const int* in_sizes, int n_in,
                              void* d_out, int out_size)
{
    (void)in_sizes; (void)n_in; (void)out_size;
    const float* x     = (const float*)d_in[0];
    const float* mask  = (const float*)d_in[1];
    const float* Wq    = (const float*)d_in[2];
    const float* bq    = (const float*)d_in[3];
    const float* Wk    = (const float*)d_in[4];
    const float* bk    = (const float*)d_in[5];
    const float* Wv    = (const float*)d_in[6];
    const float* bv    = (const float*)d_in[7];
    const float* gamma = (const float*)d_in[8];
    float* out = (float*)d_out;

    const int proj_smem = 8192 * (int)sizeof(float);   // [256][32] floats = 32 KB
    cudaFuncSetAttribute(proj_kernel, cudaFuncAttributeMaxDynamicSharedMemorySize, proj_smem);
    cudaFuncSetAttribute(attn_kernel, cudaFuncAttributeMaxDynamicSharedMemorySize, SMEM_ATTN);

    proj_kernel<<<dim3(NN / 32, BN), 256, proj_smem>>>(x, mask, Wq, bq, Wk, bk, Wv, bv);
    attn_kernel<<<dim3(NN / 128, BN), 512, SMEM_ATTN>>>(x, gamma, out);
}

// round 8
// speedup vs baseline: 2.8403x; 1.0168x over previous
#include <cuda_runtime.h>
#include <cuda_bf16.h>
#include <stdint.h>
#include <math.h>

#define BN  4
#define CCH 256
#define CQ  32
#define NN  4096
#define NT  64

// ---------------- bf16 operand globals ---------------------------------------
__device__ __align__(128) __nv_bfloat16 g_qhi[(size_t)BN * NN * CQ];
__device__ __align__(128) __nv_bfloat16 g_qlo[(size_t)BN * NN * CQ];
__device__ __align__(128) __nv_bfloat16 g_khi[(size_t)BN * NN * CQ];
__device__ __align__(128) __nv_bfloat16 g_vhi[(size_t)BN * CCH * NN];   // [b][c][n]

// ---------------- helpers ----------------------------------------------------
__device__ __forceinline__ uint32_t smem_u32(const void* p) {
    uint32_t a;
    asm("{ .reg .u64 t; cvta.to.shared.u64 t, %1; cvt.u32.u64 %0, t; }" : "=r"(a) : "l"(p));
    return a;
}
__device__ __forceinline__ uint32_t swz(uint32_t x) { return x ^ ((x >> 3) & 0x70); }

__device__ __forceinline__ void cp16(uint32_t dst, const void* src) {
    asm volatile("cp.async.cg.shared.global [%0], [%1], 16;" :: "r"(dst), "l"(src) : "memory");
}
__device__ __forceinline__ void cp_commit() { asm volatile("cp.async.commit_group;" ::: "memory"); }
__device__ __forceinline__ void cp_wait0()  { asm volatile("cp.async.wait_group 0;" ::: "memory"); }

__device__ __forceinline__ void ldm_x4(uint32_t* r, uint32_t addr) {
    asm volatile("ldmatrix.sync.aligned.m8n8.x4.shared.b16 {%0,%1,%2,%3}, [%4];"
                 : "=r"(r[0]), "=r"(r[1]), "=r"(r[2]), "=r"(r[3]) : "r"(addr));
}
__device__ __forceinline__ void mma16816(float* c, const uint32_t* a, uint32_t b0, uint32_t b1) {
    asm volatile("mma.sync.aligned.m16n8k16.row.col.f32.bf16.bf16.f32 "
                 "{%0,%1,%2,%3}, {%4,%5,%6,%7}, {%8,%9}, {%0,%1,%2,%3};"
                 : "+f"(c[0]), "+f"(c[1]), "+f"(c[2]), "+f"(c[3])
                 : "r"(a[0]), "r"(a[1]), "r"(a[2]), "r"(a[3]), "r"(b0), "r"(b1));
}
__device__ __forceinline__ uint32_t packbf2(float a, float b) {
    __nv_bfloat162 t = __floats2bfloat162_rn(a, b);
    return *(uint32_t*)&t;
}

// ---------------- projection kernel (FFMA, 2 pixels/thread) ------------------
__device__ __forceinline__ void proj_quad2(const float4* __restrict__ W4, int o0,
                                           const float* __restrict__ bias,
                                           const float* __restrict__ xs, int j,
                                           float acc[2][4])
{
#pragma unroll
    for (int r = 0; r < 4; r++) { acc[0][r] = bias[o0 + r]; acc[1][r] = bias[o0 + r]; }
#pragma unroll 4
    for (int c4 = 0; c4 < CCH / 4; c4++) {
        float a0 = xs[(c4 * 4 + 0) * 64 + j];
        float a1 = xs[(c4 * 4 + 1) * 64 + j];
        float a2 = xs[(c4 * 4 + 2) * 64 + j];
        float a3 = xs[(c4 * 4 + 3) * 64 + j];
        float b0 = xs[(c4 * 4 + 0) * 64 + j + 32];
        float b1 = xs[(c4 * 4 + 1) * 64 + j + 32];
        float b2 = xs[(c4 * 4 + 2) * 64 + j + 32];
        float b3 = xs[(c4 * 4 + 3) * 64 + j + 32];
#pragma unroll
        for (int r = 0; r < 4; r++) {
            float4 w = W4[(o0 + r) * (CCH / 4) + c4];
            acc[0][r] = fmaf(w.x, a0, acc[0][r]);
            acc[0][r] = fmaf(w.y, a1, acc[0][r]);
            acc[0][r] = fmaf(w.z, a2, acc[0][r]);
            acc[0][r] = fmaf(w.w, a3, acc[0][r]);
            acc[1][r] = fmaf(w.x, b0, acc[1][r]);
            acc[1][r] = fmaf(w.y, b1, acc[1][r]);
            acc[1][r] = fmaf(w.z, b2, acc[1][r]);
            acc[1][r] = fmaf(w.w, b3, acc[1][r]);
        }
    }
}

__device__ __forceinline__ void store_q_split(size_t base, const float v[4])
{
    __nv_bfloat162 h01 = __floats2bfloat162_rn(v[0], v[1]);
    __nv_bfloat162 h23 = __floats2bfloat162_rn(v[2], v[3]);
    float l0 = v[0] - __bfloat162float(h01.x);
    float l1 = v[1] - __bfloat162float(h01.y);
    float l2 = v[2] - __bfloat162float(h23.x);
    float l3 = v[3] - __bfloat162float(h23.y);
    __nv_bfloat162 L01 = __floats2bfloat162_rn(l0, l1);
    __nv_bfloat162 L23 = __floats2bfloat162_rn(l2, l3);
    *(uint2*)&g_qhi[base] = make_uint2(*(uint32_t*)&h01, *(uint32_t*)&h23);
    *(uint2*)&g_qlo[base] = make_uint2(*(uint32_t*)&L01, *(uint32_t*)&L23);
}
__device__ __forceinline__ void store_k_hi(size_t base, const float v[4])
{
    __nv_bfloat162 h01 = __floats2bfloat162_rn(v[0], v[1]);
    __nv_bfloat162 h23 = __floats2bfloat162_rn(v[2], v[3]);
    *(uint2*)&g_khi[base] = make_uint2(*(uint32_t*)&h01, *(uint32_t*)&h23);
}

__global__ __launch_bounds__(256, 2) void proj_kernel(
    const float* __restrict__ x, const float* __restrict__ mask,
    const float* __restrict__ Wq, const float* __restrict__ bq,
    const float* __restrict__ Wk, const float* __restrict__ bk,
    const float* __restrict__ Wv, const float* __restrict__ bv)
{
    extern __shared__ float xs[];   // [256][64] floats = 64 KB
    const int b   = blockIdx.y;
    const int n0  = blockIdx.x * 64;
    const int tid = threadIdx.x;

    const float* xb = x + (size_t)b * CCH * NN;
    for (int idx = tid; idx < 4096; idx += 256) {
        int c = idx >> 4, f = idx & 15;
        ((float4*)xs)[c * 16 + f] = *(const float4*)(xb + (size_t)c * NN + n0 + f * 4);
    }
    __syncthreads();

    const int j  = tid & 31;
    const int og = tid >> 5;          // 0..7 (warp-uniform)
    const int n  = n0 + j;
    const float m0 = mask[b * NN + n];
    const float m1 = mask[b * NN + n + 32];

    float acc[2][4], vm[4];

    // q
    proj_quad2((const float4*)Wq, og * 4, bq, xs, j, acc);
#pragma unroll
    for (int r = 0; r < 4; r++) vm[r] = acc[0][r] * m0;
    store_q_split(((size_t)(b * NN + n)) * CQ + og * 4, vm);
#pragma unroll
    for (int r = 0; r < 4; r++) vm[r] = acc[1][r] * m1;
    store_q_split(((size_t)(b * NN + n + 32)) * CQ + og * 4, vm);

    // k (hi only)
    proj_quad2((const float4*)Wk, og * 4, bk, xs, j, acc);
#pragma unroll
    for (int r = 0; r < 4; r++) vm[r] = acc[0][r] * m0;
    store_k_hi(((size_t)(b * NN + n)) * CQ + og * 4, vm);
#pragma unroll
    for (int r = 0; r < 4; r++) vm[r] = acc[1][r] * m1;
    store_k_hi(((size_t)(b * NN + n + 32)) * CQ + og * 4, vm);

    // v: 8 quads
#pragma unroll 2
    for (int p = 0; p < 8; p++) {
        int o0 = og * 4 + p * 32;
        proj_quad2((const float4*)Wv, o0, bv, xs, j, acc);
#pragma unroll
        for (int r = 0; r < 4; r++) {
            g_vhi[((size_t)(b * CCH + o0 + r)) * NN + n]      = __float2bfloat16(acc[0][r]);
            g_vhi[((size_t)(b * CCH + o0 + r)) * NN + n + 32] = __float2bfloat16(acc[1][r]);
        }
    }
}

// ---------------- mma.sync flash attention -----------------------------------
//   sQ: 128 rows [32 hi | 32 lo] bf16            (16 KB)
//   sK: 2 x 64 rows [32 hi] (128B row stride)    (16 KB alloc, hi half used)
//   sV: 2 x 256 rows [64 j bf16]                 (64 KB)

#define OFF_Q 0
#define OFF_K 16384
#define OFF_V 32768
#define SMEM_ATTN 98304

__device__ __forceinline__ void load_kv_tile(uint32_t sb, int b, int j0, int buf, int tid)
{
    if (tid < 256) {   // K hi: 64 rows x 4 chunks
        int row = tid >> 2, c8 = tid & 3;
        const __nv_bfloat16* src = g_khi + ((size_t)(b * NN) + j0 + row) * CQ + c8 * 8;
        cp16(sb + OFF_K + buf * 8192 + swz(row * 128 + c8 * 16), src);
    }
#pragma unroll
    for (int q = 0; q < 4; q++) {   // V: 2048 chunks
        int idx = tid + q * 512;
        int c = idx >> 3, c8 = idx & 7;
        const __nv_bfloat16* src = g_vhi + ((size_t)(b * CCH) + c) * NN + j0 + c8 * 8;
        cp16(sb + OFF_V + buf * 32768 + swz(c * 128 + c8 * 16), src);
    }
}

__global__ __launch_bounds__(512, 1) void attn_kernel(
    const float* __restrict__ x, const float* __restrict__ gamma_p,
    float* __restrict__ out)
{
    extern __shared__ char smc[];
    const uint32_t sb = smem_u32(smc);
    const int b    = blockIdx.y;
    const int i0   = blockIdx.x * 128;
    const int tid  = threadIdx.x;
    const int lane = tid & 31;
    const int wid  = tid >> 5;
    const int mw   = wid & 7;    // row block (16 rows)
    const int ch   = wid >> 3;   // col half (128 cols)

    // ---- prologue: Q + K/V tile 0 ------------------------------------------
#pragma unroll
    for (int q = 0; q < 2; q++) {   // Q hi/lo: 1024 chunks
        int idx = tid + q * 512;
        int row = idx >> 3, c8 = idx & 7;
        const __nv_bfloat16* src = (c8 < 4 ? g_qhi : g_qlo)
            + ((size_t)(b * NN) + i0 + row) * CQ + (c8 & 3) * 8;
        cp16(sb + OFF_Q + swz(row * 128 + (c8 < 4 ? 0 : 64) + (c8 & 3) * 16), src);
    }
    load_kv_tile(sb, b, 0, 0, tid);
    cp_commit();
    cp_wait0();
    __syncthreads();

    // ---- Q A-fragments ------------------------------------------------------
    const int arow  = mw * 16 + (lane & 7) + 8 * ((lane >> 3) & 1);
    const int acol8 = 8 * (lane >> 4);
    uint32_t qh[2][4], ql[2][4];
#pragma unroll
    for (int kst = 0; kst < 2; kst++) {
        ldm_x4(qh[kst], sb + OFF_Q + swz(arow * 128 + (kst * 16 + acol8) * 2));
        ldm_x4(ql[kst], sb + OFF_Q + swz(arow * 128 + 64 + (kst * 16 + acol8) * 2));
    }

    const int brow  = (lane & 7) + 8 * (lane >> 4);
    const int bcol8 = 8 * ((lane >> 3) & 1);

    float O[16][4];
#pragma unroll
    for (int n = 0; n < 16; n++)
#pragma unroll
        for (int r = 0; r < 4; r++) O[n][r] = 0.f;
    float ls0 = 0.f, ls1 = 0.f;

    for (int jt = 0; jt < NT; jt++) {
        const int buf = jt & 1;
        if (jt + 1 < NT) { load_kv_tile(sb, b, (jt + 1) * 64, (jt + 1) & 1, tid); cp_commit(); }

        const uint32_t kb = sb + OFF_K + buf * 8192;
        const uint32_t vb = sb + OFF_V + buf * 32768;

#pragma unroll
        for (int h = 0; h < 2; h++) {
            float C[4][4];
#pragma unroll
            for (int n = 0; n < 4; n++)
#pragma unroll
                for (int r = 0; r < 4; r++) C[n][r] = 0.f;

            // ---- S = (Qhi + Qlo) * Khi ----
#pragma unroll
            for (int p2 = 0; p2 < 2; p2++) {
                const int jb = h * 32 + p2 * 16;
#pragma unroll
                for (int kst = 0; kst < 2; kst++) {
                    uint32_t khf[4];
                    ldm_x4(khf, kb + swz((jb + brow) * 128 + (kst * 16 + bcol8) * 2));
                    mma16816(C[p2 * 2 + 0], qh[kst], khf[0], khf[1]);
                    mma16816(C[p2 * 2 + 1], qh[kst], khf[2], khf[3]);
                    mma16816(C[p2 * 2 + 0], ql[kst], khf[0], khf[1]);
                    mma16816(C[p2 * 2 + 1], ql[kst], khf[2], khf[3]);
                }
            }

            // ---- exp + pack P (RN bf16) ----
            uint32_t ph[2][4];
#pragma unroll
            for (int t = 0; t < 2; t++) {
                float e[8];
#pragma unroll
                for (int r = 0; r < 4; r++) e[r]     = __expf(C[2 * t][r]);
#pragma unroll
                for (int r = 0; r < 4; r++) e[4 + r] = __expf(C[2 * t + 1][r]);
                ls0 += e[0] + e[1] + e[4] + e[5];
                ls1 += e[2] + e[3] + e[6] + e[7];
                ph[t][0] = packbf2(e[0], e[1]); ph[t][1] = packbf2(e[2], e[3]);
                ph[t][2] = packbf2(e[4], e[5]); ph[t][3] = packbf2(e[6], e[7]);
            }

            // ---- O += P * V ----
#pragma unroll
            for (int t = 0; t < 2; t++) {
                const int k0 = h * 32 + t * 16;
#pragma unroll
                for (int cbp = 0; cbp < 8; cbp++) {
                    const int cb = ch * 128 + cbp * 16;
                    uint32_t vf[4];
                    ldm_x4(vf, vb + swz((cb + brow) * 128 + (k0 + bcol8) * 2));
                    mma16816(O[cbp * 2 + 0], ph[t], vf[0], vf[1]);
                    mma16816(O[cbp * 2 + 1], ph[t], vf[2], vf[3]);
                }
            }
        }

        if (jt + 1 < NT) { cp_wait0(); __syncthreads(); }
    }

    // ---- epilogue ------------------------------------------------------------
    ls0 += __shfl_xor_sync(0xffffffffu, ls0, 1);
    ls0 += __shfl_xor_sync(0xffffffffu, ls0, 2);
    ls1 += __shfl_xor_sync(0xffffffffu, ls1, 1);
    ls1 += __shfl_xor_sync(0xffffffffu, ls1, 2);
    const float linv0 = 1.f / ls0;
    const float linv1 = 1.f / ls1;
    const float g = *gamma_p;
    const int r0 = i0 + mw * 16 + (lane >> 2);

#pragma unroll
    for (int nb = 0; nb < 16; nb++) {
        const int cc = ch * 128 + nb * 8 + (lane & 3) * 2;
        const size_t b0 = ((size_t)(b * CCH + cc)) * NN + r0;
        const size_t b1 = b0 + NN;
        out[b0]     = fmaf(g, O[nb][0] * linv0, x[b0]);
        out[b1]     = fmaf(g, O[nb][1] * linv0, x[b1]);
        out[b0 + 8] = fmaf(g, O[nb][2] * linv1, x[b0 + 8]);
        out[b1 + 8] = fmaf(g, O[nb][3] * linv1, x[b1 + 8]);
    }
}

// ---------------- launch -----------------------------------------------------
extern "C" void kernel_launch(void* const* d_in, const int* in_sizes, int n_in,
                              void* d_out, int out_size)
{
    (void)in_sizes; (void)n_in; (void)out_size;
    const float* x     = (const float*)d_in[0];
    const float* mask  = (const float*)d_in[1];
    const float* Wq    = (const float*)d_in[2];
    const float* bq    = (const float*)d_in[3];
    const float* Wk    = (const float*)d_in[4];
    const float* bk    = (const float*)d_in[5];
    const float* Wv    = (const float*)d_in[6];
    const float* bv    = (const float*)d_in[7];
    const float* gamma = (const float*)d_in[8];
    float* out = (float*)d_out;

    const int proj_smem = 16384 * (int)sizeof(float);   // [256][64] floats = 64 KB
    cudaFuncSetAttribute(proj_kernel, cudaFuncAttributeMaxDynamicSharedMemorySize, proj_smem);
    cudaFuncSetAttribute(attn_kernel, cudaFuncAttributeMaxDynamicSharedMemorySize, SMEM_ATTN);

    proj_kernel<<<dim3(NN / 64, BN), 256, proj_smem>>>(x, mask, Wq, bq, Wk, bk, Wv, bv);
    attn_kernel<<<dim3(NN / 128, BN), 512, SMEM_ATTN>>>(x, gamma, out);
}

// round 9
// speedup vs baseline: 4.4912x; 1.5813x over previous
#include <cuda_runtime.h>
#include <cuda_bf16.h>
#include <stdint.h>
#include <math.h>

#define BN  4
#define CCH 256
#define CQ  32
#define NN  4096
#define NT  64

// ---------------- bf16 operand globals ---------------------------------------
__device__ __align__(128) __nv_bfloat16 g_qhi[(size_t)BN * NN * CQ];
__device__ __align__(128) __nv_bfloat16 g_qlo[(size_t)BN * NN * CQ];
__device__ __align__(128) __nv_bfloat16 g_khi[(size_t)BN * NN * CQ];
__device__ __align__(128) __nv_bfloat16 g_vhi[(size_t)BN * CCH * NN];   // [b][c][n]

// ---------------- helpers ----------------------------------------------------
__device__ __forceinline__ uint32_t smem_u32(const void* p) {
    uint32_t a;
    asm("{ .reg .u64 t; cvta.to.shared.u64 t, %1; cvt.u32.u64 %0, t; }" : "=r"(a) : "l"(p));
    return a;
}
__device__ __forceinline__ uint32_t swz(uint32_t x) { return x ^ ((x >> 3) & 0x70); }

__device__ __forceinline__ void cp16(uint32_t dst, const void* src) {
    asm volatile("cp.async.cg.shared.global [%0], [%1], 16;" :: "r"(dst), "l"(src) : "memory");
}
__device__ __forceinline__ void cp_commit() { asm volatile("cp.async.commit_group;" ::: "memory"); }
__device__ __forceinline__ void cp_wait0()  { asm volatile("cp.async.wait_group 0;" ::: "memory"); }

__device__ __forceinline__ void ldm_x4(uint32_t* r, uint32_t addr) {
    asm volatile("ldmatrix.sync.aligned.m8n8.x4.shared.b16 {%0,%1,%2,%3}, [%4];"
                 : "=r"(r[0]), "=r"(r[1]), "=r"(r[2]), "=r"(r[3]) : "r"(addr));
}
__device__ __forceinline__ void mma16816(float* c, const uint32_t* a, uint32_t b0, uint32_t b1) {
    asm volatile("mma.sync.aligned.m16n8k16.row.col.f32.bf16.bf16.f32 "
                 "{%0,%1,%2,%3}, {%4,%5,%6,%7}, {%8,%9}, {%0,%1,%2,%3};"
                 : "+f"(c[0]), "+f"(c[1]), "+f"(c[2]), "+f"(c[3])
                 : "r"(a[0]), "r"(a[1]), "r"(a[2]), "r"(a[3]), "r"(b0), "r"(b1));
}
__device__ __forceinline__ uint32_t packbf2(float a, float b) {
    __nv_bfloat162 t = __floats2bfloat162_rn(a, b);
    return *(uint32_t*)&t;
}

// ---------------- projection kernel ------------------------------------------
// x tile transposed in smem: x4s[px * 64 + (c4 ^ px)] (float4 over channels),
// XOR swizzle -> conflict-free LDS.128. 2 pixels/thread, 4 outputs/thread.

__device__ __forceinline__ void proj_quad2(const float4* __restrict__ W4, int o0,
                                           const float* __restrict__ bias,
                                           const float4* __restrict__ x4s, int j,
                                           float acc[2][4])
{
#pragma unroll
    for (int r = 0; r < 4; r++) { acc[0][r] = bias[o0 + r]; acc[1][r] = bias[o0 + r]; }
#pragma unroll 8
    for (int c4 = 0; c4 < CCH / 4; c4++) {
        float4 xa = x4s[j * 64 + (c4 ^ j)];
        float4 xb = x4s[(j + 32) * 64 + (c4 ^ (j + 32))];
#pragma unroll
        for (int r = 0; r < 4; r++) {
            float4 w = W4[(o0 + r) * (CCH / 4) + c4];
            acc[0][r] = fmaf(w.x, xa.x, acc[0][r]);
            acc[0][r] = fmaf(w.y, xa.y, acc[0][r]);
            acc[0][r] = fmaf(w.z, xa.z, acc[0][r]);
            acc[0][r] = fmaf(w.w, xa.w, acc[0][r]);
            acc[1][r] = fmaf(w.x, xb.x, acc[1][r]);
            acc[1][r] = fmaf(w.y, xb.y, acc[1][r]);
            acc[1][r] = fmaf(w.z, xb.z, acc[1][r]);
            acc[1][r] = fmaf(w.w, xb.w, acc[1][r]);
        }
    }
}

__device__ __forceinline__ void store_q_split(size_t base, const float v[4])
{
    __nv_bfloat162 h01 = __floats2bfloat162_rn(v[0], v[1]);
    __nv_bfloat162 h23 = __floats2bfloat162_rn(v[2], v[3]);
    float l0 = v[0] - __bfloat162float(h01.x);
    float l1 = v[1] - __bfloat162float(h01.y);
    float l2 = v[2] - __bfloat162float(h23.x);
    float l3 = v[3] - __bfloat162float(h23.y);
    __nv_bfloat162 L01 = __floats2bfloat162_rn(l0, l1);
    __nv_bfloat162 L23 = __floats2bfloat162_rn(l2, l3);
    *(uint2*)&g_qhi[base] = make_uint2(*(uint32_t*)&h01, *(uint32_t*)&h23);
    *(uint2*)&g_qlo[base] = make_uint2(*(uint32_t*)&L01, *(uint32_t*)&L23);
}
__device__ __forceinline__ void store_k_hi(size_t base, const float v[4])
{
    __nv_bfloat162 h01 = __floats2bfloat162_rn(v[0], v[1]);
    __nv_bfloat162 h23 = __floats2bfloat162_rn(v[2], v[3]);
    *(uint2*)&g_khi[base] = make_uint2(*(uint32_t*)&h01, *(uint32_t*)&h23);
}

__global__ __launch_bounds__(256, 2) void proj_kernel(
    const float* __restrict__ x, const float* __restrict__ mask,
    const float* __restrict__ Wq, const float* __restrict__ bq,
    const float* __restrict__ Wk, const float* __restrict__ bk,
    const float* __restrict__ Wv, const float* __restrict__ bv)
{
    extern __shared__ float4 x4s[];   // [64 px][64 c4] = 64 KB, XOR-swizzled
    const int b   = blockIdx.y;
    const int n0  = blockIdx.x * 64;
    const int tid = threadIdx.x;

    const float* xb = x + (size_t)b * CCH * NN;
    // stage: each (px, c4) gathers 4 channel values for one pixel
    for (int idx = tid; idx < 4096; idx += 256) {
        int px = idx & 63, c4 = idx >> 6;
        float4 v;
        v.x = xb[(size_t)(c4 * 4 + 0) * NN + n0 + px];
        v.y = xb[(size_t)(c4 * 4 + 1) * NN + n0 + px];
        v.z = xb[(size_t)(c4 * 4 + 2) * NN + n0 + px];
        v.w = xb[(size_t)(c4 * 4 + 3) * NN + n0 + px];
        x4s[px * 64 + (c4 ^ px)] = v;
    }
    __syncthreads();

    const int j  = tid & 31;
    const int og = tid >> 5;          // 0..7 (warp-uniform)
    const int n  = n0 + j;
    const float m0 = mask[b * NN + n];
    const float m1 = mask[b * NN + n + 32];

    float acc[2][4], vm[4];

    // q
    proj_quad2((const float4*)Wq, og * 4, bq, x4s, j, acc);
#pragma unroll
    for (int r = 0; r < 4; r++) vm[r] = acc[0][r] * m0;
    store_q_split(((size_t)(b * NN + n)) * CQ + og * 4, vm);
#pragma unroll
    for (int r = 0; r < 4; r++) vm[r] = acc[1][r] * m1;
    store_q_split(((size_t)(b * NN + n + 32)) * CQ + og * 4, vm);

    // k (hi only)
    proj_quad2((const float4*)Wk, og * 4, bk, x4s, j, acc);
#pragma unroll
    for (int r = 0; r < 4; r++) vm[r] = acc[0][r] * m0;
    store_k_hi(((size_t)(b * NN + n)) * CQ + og * 4, vm);
#pragma unroll
    for (int r = 0; r < 4; r++) vm[r] = acc[1][r] * m1;
    store_k_hi(((size_t)(b * NN + n + 32)) * CQ + og * 4, vm);

    // v: 8 quads
#pragma unroll 2
    for (int p = 0; p < 8; p++) {
        int o0 = og * 4 + p * 32;
        proj_quad2((const float4*)Wv, o0, bv, x4s, j, acc);
#pragma unroll
        for (int r = 0; r < 4; r++) {
            g_vhi[((size_t)(b * CCH + o0 + r)) * NN + n]      = __float2bfloat16(acc[0][r]);
            g_vhi[((size_t)(b * CCH + o0 + r)) * NN + n + 32] = __float2bfloat16(acc[1][r]);
        }
    }
}

// ---------------- mma.sync flash attention (M=64, 256 thr, 2 CTA/SM) ---------
//   sQ: 64 rows [32 hi | 32 lo] bf16             (8 KB)
//   sK: 2 x 64 rows [32 hi] (128B rows)          (16 KB)
//   sV: 2 x 256 rows [64 j bf16]                 (64 KB)

#define OFF_Q 0
#define OFF_K 8192
#define OFF_V 24576
#define SMEM_ATTN 90112

__device__ __forceinline__ void load_kv_tile(uint32_t sb, int b, int j0, int buf, int tid)
{
    {   // K hi: 256 chunks, one per thread
        int row = tid >> 2, c8 = tid & 3;
        const __nv_bfloat16* src = g_khi + ((size_t)(b * NN) + j0 + row) * CQ + c8 * 8;
        cp16(sb + OFF_K + buf * 8192 + swz(row * 128 + c8 * 16), src);
    }
#pragma unroll
    for (int q = 0; q < 8; q++) {   // V: 2048 chunks
        int idx = tid + q * 256;
        int c = idx >> 3, c8 = idx & 7;
        const __nv_bfloat16* src = g_vhi + ((size_t)(b * CCH) + c) * NN + j0 + c8 * 8;
        cp16(sb + OFF_V + buf * 32768 + swz(c * 128 + c8 * 16), src);
    }
}

__global__ __launch_bounds__(256, 2) void attn_kernel(
    const float* __restrict__ x, const float* __restrict__ gamma_p,
    float* __restrict__ out)
{
    extern __shared__ char smc[];
    const uint32_t sb = smem_u32(smc);
    const int b    = blockIdx.y;
    const int i0   = blockIdx.x * 64;
    const int tid  = threadIdx.x;
    const int lane = tid & 31;
    const int wid  = tid >> 5;
    const int mw   = wid & 3;    // row block (16 rows, 64 total)
    const int ch   = wid >> 2;   // col half (128 cols)

    // ---- prologue: Q + K/V tile 0 ------------------------------------------
#pragma unroll
    for (int q = 0; q < 2; q++) {   // Q hi/lo: 512 chunks
        int idx = tid + q * 256;
        int row = idx >> 3, c8 = idx & 7;
        const __nv_bfloat16* src = (c8 < 4 ? g_qhi : g_qlo)
            + ((size_t)(b * NN) + i0 + row) * CQ + (c8 & 3) * 8;
        cp16(sb + OFF_Q + swz(row * 128 + (c8 < 4 ? 0 : 64) + (c8 & 3) * 16), src);
    }
    load_kv_tile(sb, b, 0, 0, tid);
    cp_commit();
    cp_wait0();
    __syncthreads();

    // ---- Q A-fragments ------------------------------------------------------
    const int arow  = mw * 16 + (lane & 7) + 8 * ((lane >> 3) & 1);
    const int acol8 = 8 * (lane >> 4);
    uint32_t qh[2][4], ql[2][4];
#pragma unroll
    for (int kst = 0; kst < 2; kst++) {
        ldm_x4(qh[kst], sb + OFF_Q + swz(arow * 128 + (kst * 16 + acol8) * 2));
        ldm_x4(ql[kst], sb + OFF_Q + swz(arow * 128 + 64 + (kst * 16 + acol8) * 2));
    }

    const int brow  = (lane & 7) + 8 * (lane >> 4);
    const int bcol8 = 8 * ((lane >> 3) & 1);

    float O[16][4];
#pragma unroll
    for (int n = 0; n < 16; n++)
#pragma unroll
        for (int r = 0; r < 4; r++) O[n][r] = 0.f;
    float ls0 = 0.f, ls1 = 0.f;

    for (int jt = 0; jt < NT; jt++) {
        const int buf = jt & 1;
        if (jt + 1 < NT) { load_kv_tile(sb, b, (jt + 1) * 64, (jt + 1) & 1, tid); cp_commit(); }

        const uint32_t kb = sb + OFF_K + buf * 8192;
        const uint32_t vb = sb + OFF_V + buf * 32768;

#pragma unroll
        for (int h = 0; h < 2; h++) {
            float C[4][4];
#pragma unroll
            for (int n = 0; n < 4; n++)
#pragma unroll
                for (int r = 0; r < 4; r++) C[n][r] = 0.f;

            // ---- S = (Qhi + Qlo) * Khi ----
#pragma unroll
            for (int p2 = 0; p2 < 2; p2++) {
                const int jb = h * 32 + p2 * 16;
#pragma unroll
                for (int kst = 0; kst < 2; kst++) {
                    uint32_t khf[4];
                    ldm_x4(khf, kb + swz((jb + brow) * 128 + (kst * 16 + bcol8) * 2));
                    mma16816(C[p2 * 2 + 0], qh[kst], khf[0], khf[1]);
                    mma16816(C[p2 * 2 + 1], qh[kst], khf[2], khf[3]);
                    mma16816(C[p2 * 2 + 0], ql[kst], khf[0], khf[1]);
                    mma16816(C[p2 * 2 + 1], ql[kst], khf[2], khf[3]);
                }
            }

            // ---- exp + pack P (RN bf16) ----
            uint32_t ph[2][4];
#pragma unroll
            for (int t = 0; t < 2; t++) {
                float e[8];
#pragma unroll
                for (int r = 0; r < 4; r++) e[r]     = __expf(C[2 * t][r]);
#pragma unroll
                for (int r = 0; r < 4; r++) e[4 + r] = __expf(C[2 * t + 1][r]);
                ls0 += e[0] + e[1] + e[4] + e[5];
                ls1 += e[2] + e[3] + e[6] + e[7];
                ph[t][0] = packbf2(e[0], e[1]); ph[t][1] = packbf2(e[2], e[3]);
                ph[t][2] = packbf2(e[4], e[5]); ph[t][3] = packbf2(e[6], e[7]);
            }

            // ---- O += P * V ----
#pragma unroll
            for (int t = 0; t < 2; t++) {
                const int k0 = h * 32 + t * 16;
#pragma unroll
                for (int cbp = 0; cbp < 8; cbp++) {
                    const int cb = ch * 128 + cbp * 16;
                    uint32_t vf[4];
                    ldm_x4(vf, vb + swz((cb + brow) * 128 + (k0 + bcol8) * 2));
                    mma16816(O[cbp * 2 + 0], ph[t], vf[0], vf[1]);
                    mma16816(O[cbp * 2 + 1], ph[t], vf[2], vf[3]);
                }
            }
        }

        if (jt + 1 < NT) { cp_wait0(); __syncthreads(); }
    }

    // ---- epilogue ------------------------------------------------------------
    ls0 += __shfl_xor_sync(0xffffffffu, ls0, 1);
    ls0 += __shfl_xor_sync(0xffffffffu, ls0, 2);
    ls1 += __shfl_xor_sync(0xffffffffu, ls1, 1);
    ls1 += __shfl_xor_sync(0xffffffffu, ls1, 2);
    const float linv0 = 1.f / ls0;
    const float linv1 = 1.f / ls1;
    const float g = *gamma_p;
    const int r0 = i0 + mw * 16 + (lane >> 2);

#pragma unroll
    for (int nb = 0; nb < 16; nb++) {
        const int cc = ch * 128 + nb * 8 + (lane & 3) * 2;
        const size_t b0 = ((size_t)(b * CCH + cc)) * NN + r0;
        const size_t b1 = b0 + NN;
        out[b0]     = fmaf(g, O[nb][0] * linv0, x[b0]);
        out[b1]     = fmaf(g, O[nb][1] * linv0, x[b1]);
        out[b0 + 8] = fmaf(g, O[nb][2] * linv1, x[b0 + 8]);
        out[b1 + 8] = fmaf(g, O[nb][3] * linv1, x[b1 + 8]);
    }
}

// ---------------- launch -----------------------------------------------------
extern "C" void kernel_launch(void* const* d_in, const int* in_sizes, int n_in,
                              void* d_out, int out_size)
{
    (void)in_sizes; (void)n_in; (void)out_size;
    const float* x     = (const float*)d_in[0];
    const float* mask  = (const float*)d_in[1];
    const float* Wq    = (const float*)d_in[2];
    const float* bq    = (const float*)d_in[3];
    const float* Wk    = (const float*)d_in[4];
    const float* bk    = (const float*)d_in[5];
    const float* Wv    = (const float*)d_in[6];
    const float* bv    = (const float*)d_in[7];
    const float* gamma = (const float*)d_in[8];
    float* out = (float*)d_out;

    const int proj_smem = 4096 * (int)sizeof(float4);   // 64 KB
    cudaFuncSetAttribute(proj_kernel, cudaFuncAttributeMaxDynamicSharedMemorySize, proj_smem);
    cudaFuncSetAttribute(attn_kernel, cudaFuncAttributeMaxDynamicSharedMemorySize, SMEM_ATTN);

    proj_kernel<<<dim3(NN / 64, BN), 256, proj_smem>>>(x, mask, Wq, bq, Wk, bk, Wv, bv);
    attn_kernel<<<dim3(NN / 64, BN), 256, SMEM_ATTN>>>(x, gamma, out);
}